// round 16
// baseline (speedup 1.0000x reference)
#include <cuda_runtime.h>
#include <cstdint>

#define NB 16
#define NL 1024
#define ND 512
#define NH 256
#define NK 4
#define NROWS (NB * NL)   // 16384

// ---------------- scratch (static device globals; no allocs) ----------------
__device__ float g_sel [NROWS * NK];     // softmax selections     (256 KB)
__device__ float g_uin [NROWS * NH];     // x @ W_B^T              (16 MB)
__device__ float g_invn[NROWS * NH];     // 1/norm per (row, j)    (16 MB)

// ---------------- helpers ----------------------------------------------------
__device__ __forceinline__ float fast_lg2(float x) {
    float r; asm("lg2.approx.f32 %0, %1;" : "=f"(r) : "f"(x)); return r;
}
__device__ __forceinline__ float fast_ex2(float x) {
    float r; asm("ex2.approx.f32 %0, %1;" : "=f"(r) : "f"(x)); return r;
}
__device__ __forceinline__ uint32_t smem_u32(const void* p) {
    uint32_t a;
    asm("{ .reg .u64 t; cvta.to.shared.u64 t, %1; cvt.u32.u64 %0, t; }"
        : "=r"(a) : "l"(p));
    return a;
}
__device__ __forceinline__ uint32_t mapa_u32(uint32_t a, uint32_t r) {
    uint32_t d;
    asm("mapa.shared::cluster.u32 %0, %1, %2;" : "=r"(d) : "r"(a), "r"(r));
    return d;
}
__device__ __forceinline__ void mbar_wait(uint32_t mb, uint32_t ph) {
    asm volatile(
        "{\n\t.reg .pred p;\n"
        "WL%=:\n\t"
        "mbarrier.try_wait.parity.acquire.cluster.shared::cta.b64 p, [%0], %1;\n\t"
        "@!p bra WL%=;\n\t}"
        :: "r"(mb), "r"(ph) : "memory");
}

// ---------------- kernel 1: selection logits + softmax ----------------------
__global__ __launch_bounds__(256) void sel_kernel(
    const float* __restrict__ x, const float* __restrict__ Wsel,
    const float* __restrict__ bsel)
{
    __shared__ float Ws[NK * ND];
    for (int i = threadIdx.x; i < NK * ND; i += blockDim.x) Ws[i] = Wsel[i];
    __syncthreads();

    int w = threadIdx.x >> 5, l = threadIdx.x & 31;
    int row = blockIdx.x * 8 + w;
    const float* xr = x + row * ND;

    float p0 = 0.f, p1 = 0.f, p2 = 0.f, p3 = 0.f;
    for (int d = l; d < ND; d += 32) {
        float xv = xr[d];
        p0 += xv * Ws[d];
        p1 += xv * Ws[ND + d];
        p2 += xv * Ws[2 * ND + d];
        p3 += xv * Ws[3 * ND + d];
    }
#pragma unroll
    for (int o = 16; o > 0; o >>= 1) {
        p0 += __shfl_xor_sync(0xffffffffu, p0, o);
        p1 += __shfl_xor_sync(0xffffffffu, p1, o);
        p2 += __shfl_xor_sync(0xffffffffu, p2, o);
        p3 += __shfl_xor_sync(0xffffffffu, p3, o);
    }
    if (l == 0) {
        float l0 = p0 + bsel[0], l1 = p1 + bsel[1], l2 = p2 + bsel[2], l3 = p3 + bsel[3];
        float m = fmaxf(fmaxf(l0, l1), fmaxf(l2, l3));
        float e0 = __expf(l0 - m), e1 = __expf(l1 - m), e2 = __expf(l2 - m), e3 = __expf(l3 - m);
        float inv = 1.0f / (e0 + e1 + e2 + e3);
        float4 out = make_float4(e0 * inv, e1 * inv, e2 * inv, e3 * inv);
        *reinterpret_cast<float4*>(&g_sel[row * NK]) = out;
    }
}

// ---------------- kernel 2: u = x @ W_B^T  (128x128 tile, 8x8/thread) -------
__global__ __launch_bounds__(256, 2) void uin_kernel(
    const float* __restrict__ X, const float* __restrict__ Wb)
{
    __shared__ float Xs[16][128];
    __shared__ float Wt[16][128];
    int m0 = blockIdx.x * 128;
    int n0 = blockIdx.y * 128;
    int tid = threadIdx.x;
    int tx = tid & 15, ty = tid >> 4;
    int lr = tid >> 2, lq = tid & 3;

    float acc[8][8];
#pragma unroll
    for (int r = 0; r < 8; r++)
#pragma unroll
        for (int c = 0; c < 8; c++) acc[r][c] = 0.f;

    for (int k0 = 0; k0 < ND; k0 += 16) {
        float4 x0 = *reinterpret_cast<const float4*>(&X [(m0 + lr)      * ND + k0 + lq * 4]);
        float4 x1 = *reinterpret_cast<const float4*>(&X [(m0 + 64 + lr) * ND + k0 + lq * 4]);
        float4 w0 = *reinterpret_cast<const float4*>(&Wb[(n0 + lr)      * ND + k0 + lq * 4]);
        float4 w1 = *reinterpret_cast<const float4*>(&Wb[(n0 + 64 + lr) * ND + k0 + lq * 4]);
        __syncthreads();
        Xs[lq * 4 + 0][lr] = x0.x; Xs[lq * 4 + 1][lr] = x0.y;
        Xs[lq * 4 + 2][lr] = x0.z; Xs[lq * 4 + 3][lr] = x0.w;
        Xs[lq * 4 + 0][64 + lr] = x1.x; Xs[lq * 4 + 1][64 + lr] = x1.y;
        Xs[lq * 4 + 2][64 + lr] = x1.z; Xs[lq * 4 + 3][64 + lr] = x1.w;
        Wt[lq * 4 + 0][lr] = w0.x; Wt[lq * 4 + 1][lr] = w0.y;
        Wt[lq * 4 + 2][lr] = w0.z; Wt[lq * 4 + 3][lr] = w0.w;
        Wt[lq * 4 + 0][64 + lr] = w1.x; Wt[lq * 4 + 1][64 + lr] = w1.y;
        Wt[lq * 4 + 2][64 + lr] = w1.z; Wt[lq * 4 + 3][64 + lr] = w1.w;
        __syncthreads();
#pragma unroll
        for (int kk = 0; kk < 16; kk++) {
            float4 a0 = *reinterpret_cast<const float4*>(&Xs[kk][ty * 8]);
            float4 a1 = *reinterpret_cast<const float4*>(&Xs[kk][ty * 8 + 4]);
            float4 b0 = *reinterpret_cast<const float4*>(&Wt[kk][tx * 8]);
            float4 b1 = *reinterpret_cast<const float4*>(&Wt[kk][tx * 8 + 4]);
            float av[8] = {a0.x, a0.y, a0.z, a0.w, a1.x, a1.y, a1.z, a1.w};
            float bv[8] = {b0.x, b0.y, b0.z, b0.w, b1.x, b1.y, b1.z, b1.w};
#pragma unroll
            for (int r = 0; r < 8; r++)
#pragma unroll
                for (int c = 0; c < 8; c++)
                    acc[r][c] = fmaf(av[r], bv[c], acc[r][c]);
        }
    }
#pragma unroll
    for (int r = 0; r < 8; r++) {
        float4 o0 = make_float4(acc[r][0], acc[r][1], acc[r][2], acc[r][3]);
        float4 o1 = make_float4(acc[r][4], acc[r][5], acc[r][6], acc[r][7]);
        *reinterpret_cast<float4*>(&g_uin[(m0 + ty * 8 + r) * NH + n0 + tx * 8])     = o0;
        *reinterpret_cast<float4*>(&g_uin[(m0 + ty * 8 + r) * NH + n0 + tx * 8 + 4]) = o1;
    }
}

// ---------------- kernel 3: inv_norm pre-pass (register-resident A) ---------
__global__ __launch_bounds__(256, 3) void norm_kernel(const float* __restrict__ A)
{
    int jbase = blockIdx.x * 8;
    int w = threadIdx.x >> 5, l = threadIdx.x & 31;
    int j = jbase + w;

    float4 Ar[8];
#pragma unroll
    for (int r = 0; r < 8; r++)
        Ar[r] = reinterpret_cast<const float4*>(A)[(l + 32 * r) * NH + j];

    const int rows_per_blk = NROWS / 64;       // 256
    const int row0 = blockIdx.y * rows_per_blk;
    const float ninv = -1.0f / 1.2f;

    for (int row = row0; row < row0 + rows_per_blk; row += 2) {
        float4 sA = __ldg(reinterpret_cast<const float4*>(&g_sel[row * NK]));
        float4 sB = __ldg(reinterpret_cast<const float4*>(&g_sel[(row + 1) * NK]));
        float accA = 0.f, accB = 0.f;
#pragma unroll
        for (int r = 0; r < 8; r++) {
            float a = fmaf(sA.x, Ar[r].x, fmaf(sA.y, Ar[r].y,
                      fmaf(sA.z, Ar[r].z, sA.w * Ar[r].w)));
            float b = fmaf(sB.x, Ar[r].x, fmaf(sB.y, Ar[r].y,
                      fmaf(sB.z, Ar[r].z, sB.w * Ar[r].w)));
            accA += fast_ex2(0.6f * fast_lg2(a * a));
            accB += fast_ex2(0.6f * fast_lg2(b * b));
        }
#pragma unroll
        for (int o = 16; o > 0; o >>= 1) {
            accA += __shfl_xor_sync(0xffffffffu, accA, o);
            accB += __shfl_xor_sync(0xffffffffu, accB, o);
        }
        if (l == 0) {
            g_invn[row * NH + j]       = fast_ex2(fast_lg2(accA) * ninv);
            g_invn[(row + 1) * NH + j] = fast_ex2(fast_lg2(accB) * ninv);
        }
    }
}

// ---------------- kernel 4: scan, 4 batches/cluster, parallel tails ---------
// 4 clusters x 8 CTAs = 32 CTAs. The per-step serial chain (~2400 cyc) is
// latency, not issue (R15 lesson) — amortize it over 4 batches per iter.
// Per-iter FFMA issue 2176 cyc/SMSP covers 4 steps (~540/step). Warps 0-3
// each own one batch's tail (prefetch inv/u, mbar wait, expect(t+2), pbuf
// consume, out store, h/y update) running concurrently.
__global__ __launch_bounds__(512, 1) __cluster_dims__(8, 1, 1)
void scan_kernel(const float* __restrict__ A, float* __restrict__ out)
{
    __shared__ float y_sm[4][32];
    __shared__ float pbuf[2][4][8][32];                     // [parity][batch][src][row]
    __shared__ __align__(8) unsigned long long mbar[2][4];  // [parity][batch]

    int tid = threadIdx.x;
    uint32_t rank;
    asm("mov.u32 %0, %%cluster_ctarank;" : "=r"(rank));
    int c = blockIdx.x >> 3;                 // cluster 0..3 -> batches 4c..4c+3
    int jbase = (int)rank * 32;
    int i = tid >> 1, half = tid & 1;
    int wid = tid >> 5, lane = tid & 31;

    float4 Areg[16];
#pragma unroll
    for (int q = 0; q < 16; q++)
        Areg[q] = reinterpret_cast<const float4*>(A)[i * NH + jbase + half * 16 + q];

    uint32_t mbar_s = smem_u32(mbar);
    if (tid == 0) {
#pragma unroll
        for (int m = 0; m < 8; m++)
            asm volatile("mbarrier.init.shared.b64 [%0], 1;"
                         :: "r"(mbar_s + m * 8) : "memory");
    }
    __syncthreads();
    if (tid == 0) {
#pragma unroll
        for (int m = 0; m < 8; m++)
            asm volatile("mbarrier.arrive.expect_tx.shared.b64 _, [%0], 1024;"
                         :: "r"(mbar_s + m * 8) : "memory");
    }
    __syncthreads();
    asm volatile("barrier.cluster.arrive.aligned;" ::: "memory");
    asm volatile("barrier.cluster.wait.aligned;"  ::: "memory");

    uint32_t dst = (uint32_t)(i >> 5);
    uint32_t lbase = smem_u32(pbuf) + (rank * 32u + (uint32_t)(i & 31)) * 4u;
    uint32_t raddr = mapa_u32(lbase, dst);   // parity stride 4096B, batch stride 1024B
    uint32_t rmbar = mapa_u32(mbar_s, dst);  // parity stride 32B,   batch stride 8B

    // tail-warp state: warp m (m<4) owns batch 4c+m
    const int myrowbase = (4 * c + (wid & 3)) * NL;
    float inv_c = 0.f, u_c = 0.f, h_c = 0.f;
    if (wid < 4) {
        inv_c = __ldg(&g_invn[myrowbase * NH + jbase + lane]);
        u_c   = __ldg(&g_uin [myrowbase * NH + jbase + lane]);
    }

    // s for all 4 batches
    float4 s_cur[4];
#pragma unroll
    for (int m = 0; m < 4; m++)
        s_cur[m] = __ldg(reinterpret_cast<const float4*>(&g_sel[(4 * c + m) * NL * NK]));

    for (int t = 0; t < NL; t++) {
        if (wid < 4) y_sm[wid][lane] = h_c * inv_c;
        __syncthreads();

        const int d = (t < NL - 1) ? 1 : 0;
        const int tn = t + d;
        const uint32_t poff = (uint32_t)(t & 1);

        // k-decomposed matvec + store, per batch
#pragma unroll
        for (int m = 0; m < 4; m++) {
            float k0 = 0.f, k1 = 0.f, k2 = 0.f, k3 = 0.f;
#pragma unroll
            for (int q = 0; q < 16; q++) {
                float yv = y_sm[m][half * 16 + q];
                k0 = fmaf(Areg[q].x, yv, k0);
                k1 = fmaf(Areg[q].y, yv, k1);
                k2 = fmaf(Areg[q].z, yv, k2);
                k3 = fmaf(Areg[q].w, yv, k3);
            }
            float acc = fmaf(s_cur[m].x, k0, fmaf(s_cur[m].y, k1,
                        fmaf(s_cur[m].z, k2, s_cur[m].w * k3)));
            acc += __shfl_xor_sync(0xffffffffu, acc, 1);
            if (half == 0) {
                asm volatile(
                    "st.async.shared::cluster.mbarrier::complete_tx::bytes.b32 [%0], %1, [%2];"
                    :: "r"(raddr + poff * 4096u + (uint32_t)m * 1024u),
                       "r"(__float_as_uint(acc)),
                       "r"(rmbar + poff * 32u + (uint32_t)m * 8u) : "memory");
            }
        }

        // prefetch s(t+1) for all batches (after stores, fills flight)
#pragma unroll
        for (int m = 0; m < 4; m++)
            s_cur[m] = __ldg(reinterpret_cast<const float4*>(
                &g_sel[((4 * c + m) * NL + tn) * NK]));

        // ---- parallel tails: warp m consumes batch m ----
        if (wid < 4) {
            float inv_n = __ldg(&g_invn[(myrowbase + tn) * NH + jbase + lane]);
            float u_n   = __ldg(&g_uin [(myrowbase + tn) * NH + jbase + lane]);

            const uint32_t ph = (uint32_t)((t >> 1) & 1);
            const uint32_t mb = mbar_s + poff * 32u + (uint32_t)wid * 8u;
            mbar_wait(mb, ph);
            if (lane == 0 && t + 2 < NL)
                asm volatile("mbarrier.arrive.expect_tx.shared.b64 _, [%0], 1024;"
                             :: "r"(mb) : "memory");
            const float* pb = &pbuf[poff][wid][0][lane];
            float b0 = pb[0]   + pb[32];
            float b1 = pb[64]  + pb[96];
            float b2 = pb[128] + pb[160];
            float b3 = pb[192] + pb[224];
            float hv = u_c + ((b0 + b1) + (b2 + b3));
            out[(myrowbase + t) * NH + jbase + lane] = hv;
            h_c = hv; inv_c = inv_n; u_c = u_n;
        }
    }

    asm volatile("barrier.cluster.arrive.aligned;" ::: "memory");
    asm volatile("barrier.cluster.wait.aligned;"  ::: "memory");
}

// ---------------- launch ----------------------------------------------------
extern "C" void kernel_launch(void* const* d_in, const int* in_sizes, int n_in,
                              void* d_out, int out_size)
{
    const float* x     = (const float*)d_in[0];   // (16,1024,512)
    const float* Wsel  = (const float*)d_in[1];   // (4,512)
    const float* bsel  = (const float*)d_in[2];   // (4,)
    const float* Wb    = (const float*)d_in[3];   // (256,512)
    const float* Adict = (const float*)d_in[4];   // (256,256,4)
    float* out = (float*)d_out;                   // (16,1024,256)

    sel_kernel<<<NROWS / 8, 256>>>(x, Wsel, bsel);
    uin_kernel<<<dim3(NROWS / 128, NH / 128), 256>>>(x, Wb);
    norm_kernel<<<dim3(32, 64), 256>>>(Adict);
    scan_kernel<<<4 * 8, 512>>>(Adict, out);      // 4 clusters x 8 CTAs
}

// round 17
// speedup vs baseline: 1.7891x; 1.7891x over previous
#include <cuda_runtime.h>
#include <cstdint>

#define NB 16
#define NL 1024
#define ND 512
#define NH 256
#define NK 4
#define NROWS (NB * NL)   // 16384
#define T_SPLIT 640       // scan1/norm1 cover t<640; scan2/norm2 cover the rest

// ---------------- scratch (static device globals; no allocs) ----------------
__device__ float g_sel [NROWS * NK];     // softmax selections     (256 KB)
__device__ float g_uin [NROWS * NH];     // x @ W_B^T              (16 MB)
__device__ float g_invn[NROWS * NH];     // 1/norm per (row, j)    (16 MB)
__device__ float g_h   [NB * NH];        // scan1 -> scan2 h handoff (16 KB)

// ---------------- helpers ----------------------------------------------------
__device__ __forceinline__ float fast_lg2(float x) {
    float r; asm("lg2.approx.f32 %0, %1;" : "=f"(r) : "f"(x)); return r;
}
__device__ __forceinline__ float fast_ex2(float x) {
    float r; asm("ex2.approx.f32 %0, %1;" : "=f"(r) : "f"(x)); return r;
}
__device__ __forceinline__ uint32_t smem_u32(const void* p) {
    uint32_t a;
    asm("{ .reg .u64 t; cvta.to.shared.u64 t, %1; cvt.u32.u64 %0, t; }"
        : "=r"(a) : "l"(p));
    return a;
}
__device__ __forceinline__ uint32_t mapa_u32(uint32_t a, uint32_t r) {
    uint32_t d;
    asm("mapa.shared::cluster.u32 %0, %1, %2;" : "=r"(d) : "r"(a), "r"(r));
    return d;
}
__device__ __forceinline__ void mbar_wait(uint32_t mb, uint32_t ph) {
    asm volatile(
        "{\n\t.reg .pred p;\n"
        "WL%=:\n\t"
        "mbarrier.try_wait.parity.acquire.cluster.shared::cta.b64 p, [%0], %1;\n\t"
        "@!p bra WL%=;\n\t}"
        :: "r"(mb), "r"(ph) : "memory");
}

// ---------------- kernel 1: selection logits + softmax ----------------------
__global__ __launch_bounds__(256) void sel_kernel(
    const float* __restrict__ x, const float* __restrict__ Wsel,
    const float* __restrict__ bsel)
{
    __shared__ float Ws[NK * ND];
    for (int i = threadIdx.x; i < NK * ND; i += blockDim.x) Ws[i] = Wsel[i];
    __syncthreads();

    int w = threadIdx.x >> 5, l = threadIdx.x & 31;
    int row = blockIdx.x * 8 + w;
    const float* xr = x + row * ND;

    float p0 = 0.f, p1 = 0.f, p2 = 0.f, p3 = 0.f;
    for (int d = l; d < ND; d += 32) {
        float xv = xr[d];
        p0 += xv * Ws[d];
        p1 += xv * Ws[ND + d];
        p2 += xv * Ws[2 * ND + d];
        p3 += xv * Ws[3 * ND + d];
    }
#pragma unroll
    for (int o = 16; o > 0; o >>= 1) {
        p0 += __shfl_xor_sync(0xffffffffu, p0, o);
        p1 += __shfl_xor_sync(0xffffffffu, p1, o);
        p2 += __shfl_xor_sync(0xffffffffu, p2, o);
        p3 += __shfl_xor_sync(0xffffffffu, p3, o);
    }
    if (l == 0) {
        float l0 = p0 + bsel[0], l1 = p1 + bsel[1], l2 = p2 + bsel[2], l3 = p3 + bsel[3];
        float m = fmaxf(fmaxf(l0, l1), fmaxf(l2, l3));
        float e0 = __expf(l0 - m), e1 = __expf(l1 - m), e2 = __expf(l2 - m), e3 = __expf(l3 - m);
        float inv = 1.0f / (e0 + e1 + e2 + e3);
        float4 out = make_float4(e0 * inv, e1 * inv, e2 * inv, e3 * inv);
        *reinterpret_cast<float4*>(&g_sel[row * NK]) = out;
    }
}

// ---------------- kernel 2: u = x @ W_B^T  (128x128 tile, 8x8/thread) -------
__global__ __launch_bounds__(256, 2) void uin_kernel(
    const float* __restrict__ X, const float* __restrict__ Wb)
{
    __shared__ float Xs[16][128];
    __shared__ float Wt[16][128];
    int m0 = blockIdx.x * 128;
    int n0 = blockIdx.y * 128;
    int tid = threadIdx.x;
    int tx = tid & 15, ty = tid >> 4;
    int lr = tid >> 2, lq = tid & 3;

    float acc[8][8];
#pragma unroll
    for (int r = 0; r < 8; r++)
#pragma unroll
        for (int c = 0; c < 8; c++) acc[r][c] = 0.f;

    for (int k0 = 0; k0 < ND; k0 += 16) {
        float4 x0 = *reinterpret_cast<const float4*>(&X [(m0 + lr)      * ND + k0 + lq * 4]);
        float4 x1 = *reinterpret_cast<const float4*>(&X [(m0 + 64 + lr) * ND + k0 + lq * 4]);
        float4 w0 = *reinterpret_cast<const float4*>(&Wb[(n0 + lr)      * ND + k0 + lq * 4]);
        float4 w1 = *reinterpret_cast<const float4*>(&Wb[(n0 + 64 + lr) * ND + k0 + lq * 4]);
        __syncthreads();
        Xs[lq * 4 + 0][lr] = x0.x; Xs[lq * 4 + 1][lr] = x0.y;
        Xs[lq * 4 + 2][lr] = x0.z; Xs[lq * 4 + 3][lr] = x0.w;
        Xs[lq * 4 + 0][64 + lr] = x1.x; Xs[lq * 4 + 1][64 + lr] = x1.y;
        Xs[lq * 4 + 2][64 + lr] = x1.z; Xs[lq * 4 + 3][64 + lr] = x1.w;
        Wt[lq * 4 + 0][lr] = w0.x; Wt[lq * 4 + 1][lr] = w0.y;
        Wt[lq * 4 + 2][lr] = w0.z; Wt[lq * 4 + 3][lr] = w0.w;
        Wt[lq * 4 + 0][64 + lr] = w1.x; Wt[lq * 4 + 1][64 + lr] = w1.y;
        Wt[lq * 4 + 2][64 + lr] = w1.z; Wt[lq * 4 + 3][64 + lr] = w1.w;
        __syncthreads();
#pragma unroll
        for (int kk = 0; kk < 16; kk++) {
            float4 a0 = *reinterpret_cast<const float4*>(&Xs[kk][ty * 8]);
            float4 a1 = *reinterpret_cast<const float4*>(&Xs[kk][ty * 8 + 4]);
            float4 b0 = *reinterpret_cast<const float4*>(&Wt[kk][tx * 8]);
            float4 b1 = *reinterpret_cast<const float4*>(&Wt[kk][tx * 8 + 4]);
            float av[8] = {a0.x, a0.y, a0.z, a0.w, a1.x, a1.y, a1.z, a1.w};
            float bv[8] = {b0.x, b0.y, b0.z, b0.w, b1.x, b1.y, b1.z, b1.w};
#pragma unroll
            for (int r = 0; r < 8; r++)
#pragma unroll
                for (int c = 0; c < 8; c++)
                    acc[r][c] = fmaf(av[r], bv[c], acc[r][c]);
        }
    }
#pragma unroll
    for (int r = 0; r < 8; r++) {
        float4 o0 = make_float4(acc[r][0], acc[r][1], acc[r][2], acc[r][3]);
        float4 o1 = make_float4(acc[r][4], acc[r][5], acc[r][6], acc[r][7]);
        *reinterpret_cast<float4*>(&g_uin[(m0 + ty * 8 + r) * NH + n0 + tx * 8])     = o0;
        *reinterpret_cast<float4*>(&g_uin[(m0 + ty * 8 + r) * NH + n0 + tx * 8 + 4]) = o1;
    }
}

// ---------------- kernel 3: inv_norm pre-pass over t-range [t0, t0+128*nch) -
// grid (32 jblocks, 16*nchunks); chunk = 128 rows of one batch.
__global__ __launch_bounds__(256, 3) void norm_kernel(
    const float* __restrict__ A, int t0, int nchunks)
{
    int jbase = blockIdx.x * 8;
    int batch = blockIdx.y / nchunks;
    int ch    = blockIdx.y % nchunks;
    int w = threadIdx.x >> 5, l = threadIdx.x & 31;
    int j = jbase + w;

    float4 Ar[8];
#pragma unroll
    for (int r = 0; r < 8; r++)
        Ar[r] = reinterpret_cast<const float4*>(A)[(l + 32 * r) * NH + j];

    const int row0 = batch * NL + t0 + ch * 128;
    const float ninv = -1.0f / 1.2f;

    for (int row = row0; row < row0 + 128; row += 2) {
        float4 sA = __ldg(reinterpret_cast<const float4*>(&g_sel[row * NK]));
        float4 sB = __ldg(reinterpret_cast<const float4*>(&g_sel[(row + 1) * NK]));
        float accA = 0.f, accB = 0.f;
#pragma unroll
        for (int r = 0; r < 8; r++) {
            float a = fmaf(sA.x, Ar[r].x, fmaf(sA.y, Ar[r].y,
                      fmaf(sA.z, Ar[r].z, sA.w * Ar[r].w)));
            float b = fmaf(sB.x, Ar[r].x, fmaf(sB.y, Ar[r].y,
                      fmaf(sB.z, Ar[r].z, sB.w * Ar[r].w)));
            accA += fast_ex2(0.6f * fast_lg2(a * a));
            accB += fast_ex2(0.6f * fast_lg2(b * b));
        }
#pragma unroll
        for (int o = 16; o > 0; o >>= 1) {
            accA += __shfl_xor_sync(0xffffffffu, accA, o);
            accB += __shfl_xor_sync(0xffffffffu, accB, o);
        }
        if (l == 0) {
            g_invn[row * NH + j]       = fast_ex2(fast_lg2(accA) * ninv);
            g_invn[(row + 1) * NH + j] = fast_ex2(fast_lg2(accB) * ninv);
        }
    }
}

// ---------------- kernel 4: scan over t-range [t0, t1) ----------------------
// R14 structure (2 batches/cluster, k-decomposed matvec, parallel warp0/warp1
// tails, st.async + parity tx-mbarriers). h handoff through g_h. Note: the
// last iteration of a range prefetches invn[t1] which may be unwritten when
// scan1 runs concurrently with norm2 — the value is discarded (loop ends), so
// it is correctness-irrelevant.
__global__ __launch_bounds__(512, 1) __cluster_dims__(8, 1, 1)
void scan_kernel(const float* __restrict__ A, float* __restrict__ out,
                 int t0, int t1)
{
    __shared__ float y_sm[2][32];
    __shared__ float pbuf[2][2][8][32];                     // [parity][batch][src][row]
    __shared__ __align__(8) unsigned long long mbar[2][2];  // [parity][batch]

    int tid = threadIdx.x;
    uint32_t rank;
    asm("mov.u32 %0, %%cluster_ctarank;" : "=r"(rank));
    int c = blockIdx.x >> 3;                 // cluster id -> batches 2c, 2c+1
    int jbase = (int)rank * 32;
    int i = tid >> 1, half = tid & 1;
    int wid = tid >> 5, lane = tid & 31;

    float4 Areg[16];
#pragma unroll
    for (int q = 0; q < 16; q++)
        Areg[q] = reinterpret_cast<const float4*>(A)[i * NH + jbase + half * 16 + q];

    uint32_t mbar_s = smem_u32(mbar);
    if (tid == 0) {
#pragma unroll
        for (int m = 0; m < 4; m++)
            asm volatile("mbarrier.init.shared.b64 [%0], 1;"
                         :: "r"(mbar_s + m * 8) : "memory");
    }
    __syncthreads();
    if (tid == 0) {
#pragma unroll
        for (int m = 0; m < 4; m++)
            asm volatile("mbarrier.arrive.expect_tx.shared.b64 _, [%0], 1024;"
                         :: "r"(mbar_s + m * 8) : "memory");
    }
    __syncthreads();
    asm volatile("barrier.cluster.arrive.aligned;" ::: "memory");
    asm volatile("barrier.cluster.wait.aligned;"  ::: "memory");

    uint32_t dst = (uint32_t)(i >> 5);
    uint32_t lbase = smem_u32(pbuf) + (rank * 32u + (uint32_t)(i & 31)) * 4u;
    uint32_t raddr = mapa_u32(lbase, dst);   // parity stride 2048B, batch stride 1024B
    uint32_t rmbar = mapa_u32(mbar_s, dst);  // parity stride 16B,   batch stride 8B

    const int row0base = (2 * c) * NL;
    const int row1base = (2 * c + 1) * NL;

    float4 s0 = __ldg(reinterpret_cast<const float4*>(&g_sel[(row0base + t0) * NK]));
    float4 s1 = __ldg(reinterpret_cast<const float4*>(&g_sel[(row1base + t0) * NK]));

    // per-warp batch ownership for tails: warp0 -> batch0, warp1 -> batch1
    const int mybatch = 2 * c + wid;
    const int myrowbase = (wid == 0) ? row0base : row1base;
    float inv_c = 0.f, u_c = 0.f, h_c = 0.f;
    if (wid < 2) {
        inv_c = __ldg(&g_invn[(myrowbase + t0) * NH + jbase + lane]);
        u_c   = __ldg(&g_uin [(myrowbase + t0) * NH + jbase + lane]);
        if (t0 > 0) h_c = g_h[mybatch * NH + jbase + lane];
    }

    for (int t = t0; t < t1; t++) {
        if (wid < 2) y_sm[wid][lane] = h_c * inv_c;
        __syncthreads();

        const int d = (t < NL - 1) ? 1 : 0;
        float4 s_n0 = __ldg(reinterpret_cast<const float4*>(&g_sel[(row0base + t + d) * NK]));
        float4 s_n1 = __ldg(reinterpret_cast<const float4*>(&g_sel[(row1base + t + d) * NK]));
        float inv_n = 0.f, u_n = 0.f;
        if (wid < 2) {
            inv_n = __ldg(&g_invn[(myrowbase + t + d) * NH + jbase + lane]);
            u_n   = __ldg(&g_uin [(myrowbase + t + d) * NH + jbase + lane]);
        }

        const uint32_t poff = (uint32_t)((t - t0) & 1);

        // ---- batch 0: k-decomposed matvec + store ----
        {
            float k0 = 0.f, k1 = 0.f, k2 = 0.f, k3 = 0.f;
#pragma unroll
            for (int q = 0; q < 16; q++) {
                float yv = y_sm[0][half * 16 + q];
                k0 = fmaf(Areg[q].x, yv, k0);
                k1 = fmaf(Areg[q].y, yv, k1);
                k2 = fmaf(Areg[q].z, yv, k2);
                k3 = fmaf(Areg[q].w, yv, k3);
            }
            float acc = fmaf(s0.x, k0, fmaf(s0.y, k1, fmaf(s0.z, k2, s0.w * k3)));
            acc += __shfl_xor_sync(0xffffffffu, acc, 1);
            if (half == 0) {
                asm volatile(
                    "st.async.shared::cluster.mbarrier::complete_tx::bytes.b32 [%0], %1, [%2];"
                    :: "r"(raddr + poff * 2048u), "r"(__float_as_uint(acc)),
                       "r"(rmbar + poff * 16u) : "memory");
            }
        }
        // ---- batch 1: k-decomposed matvec + store (hides batch0 flight) ----
        {
            float k0 = 0.f, k1 = 0.f, k2 = 0.f, k3 = 0.f;
#pragma unroll
            for (int q = 0; q < 16; q++) {
                float yv = y_sm[1][half * 16 + q];
                k0 = fmaf(Areg[q].x, yv, k0);
                k1 = fmaf(Areg[q].y, yv, k1);
                k2 = fmaf(Areg[q].z, yv, k2);
                k3 = fmaf(Areg[q].w, yv, k3);
            }
            float acc = fmaf(s1.x, k0, fmaf(s1.y, k1, fmaf(s1.z, k2, s1.w * k3)));
            acc += __shfl_xor_sync(0xffffffffu, acc, 1);
            if (half == 0) {
                asm volatile(
                    "st.async.shared::cluster.mbarrier::complete_tx::bytes.b32 [%0], %1, [%2];"
                    :: "r"(raddr + poff * 2048u + 1024u), "r"(__float_as_uint(acc)),
                       "r"(rmbar + poff * 16u + 8u) : "memory");
            }
        }

        // ---- parallel tails: warp0 consumes batch0, warp1 consumes batch1 --
        if (wid < 2) {
            const uint32_t ph = (uint32_t)(((t - t0) >> 1) & 1);
            const uint32_t mb = mbar_s + poff * 16u + (uint32_t)wid * 8u;
            mbar_wait(mb, ph);
            if (lane == 0 && t + 2 < t1)
                asm volatile("mbarrier.arrive.expect_tx.shared.b64 _, [%0], 1024;"
                             :: "r"(mb) : "memory");
            const float* pb = &pbuf[poff][wid][0][lane];
            float b0 = pb[0]   + pb[32];
            float b1 = pb[64]  + pb[96];
            float b2 = pb[128] + pb[160];
            float b3 = pb[192] + pb[224];
            float hv = u_c + ((b0 + b1) + (b2 + b3));
            out[(myrowbase + t) * NH + jbase + lane] = hv;
            h_c = hv; inv_c = inv_n; u_c = u_n;
        }
        s0 = s_n0; s1 = s_n1;
    }

    // h handoff for the next range
    if (wid < 2)
        g_h[mybatch * NH + jbase + lane] = h_c;

    asm volatile("barrier.cluster.arrive.aligned;" ::: "memory");
    asm volatile("barrier.cluster.wait.aligned;"  ::: "memory");
}

// ---------------- launch: fork/join overlap of norm2 with scan1 -------------
extern "C" void kernel_launch(void* const* d_in, const int* in_sizes, int n_in,
                              void* d_out, int out_size)
{
    const float* x     = (const float*)d_in[0];   // (16,1024,512)
    const float* Wsel  = (const float*)d_in[1];   // (4,512)
    const float* bsel  = (const float*)d_in[2];   // (4,)
    const float* Wb    = (const float*)d_in[3];   // (256,512)
    const float* Adict = (const float*)d_in[4];   // (256,256,4)
    float* out = (float*)d_out;                   // (16,1024,256)

    static cudaStream_t s_side = nullptr;
    static cudaEvent_t evA = nullptr, evU = nullptr, evF = nullptr, evN = nullptr;
    if (s_side == nullptr) {                      // first (non-capture) call
        cudaStreamCreateWithFlags(&s_side, cudaStreamNonBlocking);
        cudaEventCreateWithFlags(&evA, cudaEventDisableTiming);
        cudaEventCreateWithFlags(&evU, cudaEventDisableTiming);
        cudaEventCreateWithFlags(&evF, cudaEventDisableTiming);
        cudaEventCreateWithFlags(&evN, cudaEventDisableTiming);
    }

    const int NCH1 = T_SPLIT / 128;               // 5 chunks: t in [0, 640)
    const int NCH2 = (NL - T_SPLIT) / 128;        // 3 chunks: t in [640, 1024)

    // main: sel; side: uin (independent of sel) concurrent with norm1
    cudaEventRecord(evA, 0);
    cudaStreamWaitEvent(s_side, evA, 0);
    uin_kernel<<<dim3(NROWS / 128, NH / 128), 256, 0, s_side>>>(x, Wb);
    sel_kernel<<<NROWS / 8, 256>>>(x, Wsel, bsel);
    norm_kernel<<<dim3(32, 16 * NCH1), 256>>>(Adict, 0, NCH1);          // norm1

    // join uin before scan1; fork norm2 to the side stream
    cudaEventRecord(evU, s_side);
    cudaStreamWaitEvent(0, evU, 0);
    cudaEventRecord(evF, 0);
    cudaStreamWaitEvent(s_side, evF, 0);
    norm_kernel<<<dim3(32, 16 * NCH2), 256, 0, s_side>>>(Adict, T_SPLIT, NCH2); // norm2

    scan_kernel<<<(NB / 2) * 8, 512>>>(Adict, out, 0, T_SPLIT);          // scan1

    // join norm2 before scan2
    cudaEventRecord(evN, s_side);
    cudaStreamWaitEvent(0, evN, 0);
    scan_kernel<<<(NB / 2) * 8, 512>>>(Adict, out, T_SPLIT, NL);         // scan2
}